// round 16
// baseline (speedup 1.0000x reference)
#include <cuda_runtime.h>
#include <cstdint>

#define N_NODES 200000
#define DIM 64
#define NQ 4096
#define E1N 262144
#define E0N 131072
#define KSEL 10

#define OFF_REPR  (N_NODES)
#define OFF_PE    (N_NODES + N_NODES*DIM)
#define OFF_OI    (OFF_PE + NQ*KSEL*8)

#define NBI   ((N_NODES + 255)/256)
#define NB_N  (N_NODES/64)
#define NB_QT ((NQ/64)*5)
#define NB_Q2 ((E1N + E0N)/256)     // 1536 quad blocks (256 edges each)

typedef unsigned long long u64;

__device__ __forceinline__ u64 pk2(float lo, float hi) {
    u64 r; asm("mov.b64 %0, {%1, %2};" : "=l"(r) : "f"(lo), "f"(hi)); return r;
}
__device__ __forceinline__ void fma2(u64& d, u64 a, u64 b) {
    asm("fma.rn.f32x2 %0, %1, %2, %0;" : "+l"(d) : "l"(a), "l"(b));
}
__device__ __forceinline__ float2 upk(u64 v) {
    float2 r; asm("mov.b64 {%0, %1}, %2;" : "=f"(r.x), "=f"(r.y) : "l"(v)); return r;
}
__device__ __forceinline__ u64 swp(u64 v) {
    float2 f = upk(v); return pk2(f.y, f.x);
}
__device__ __forceinline__ void red2(float* p, float x, float y) {
    asm volatile("red.global.add.v2.f32 [%0], {%1, %2};" :: "l"(p), "f"(x), "f"(y) : "memory");
}

// ---------------- scratch ----------------
__device__ float    g_M [256*256];
__device__ float    g_B1[64*192];
__device__ float    g_B2[64*64];
__device__ float    g_BL[64*64];
__device__ float    g_Bq[128*320];
__device__ float    g_QT[(size_t)NQ*320];
__device__ float    g_Qk0[NQ];
__device__ float    g_nodeT[(size_t)N_NODES*192];
__device__ float    g_quad1[E1N];
__device__ float    g_quad0[E0N];
__device__ float    g_logit[E1N];
__device__ int      g_esrc[E1N];
__device__ int      g_edst[E1N];
__device__ unsigned g_segmax [N_NODES];
__device__ float    g_segsum [N_NODES];
__device__ unsigned g_segmax0[N_NODES];
__device__ float    g_segsum0[N_NODES];
__device__ int      g_has [N_NODES];
__device__ int      g_has0[N_NODES];
__device__ float    g_H1[(size_t)N_NODES*DIM];
__device__ float    g_H2[(size_t)N_NODES*DIM];
__device__ int      g_psrc[NQ*KSEL];
__device__ int      g_pdst[NQ*KSEL];
__device__ float    g_ptrans[NQ*KSEL];
__device__ int      g_chg[NQ*KSEL];
__device__ int      g_ncnt;

__device__ __forceinline__ unsigned encf(float f) {
    unsigned u = __float_as_uint(f);
    return (u & 0x80000000u) ? ~u : (u | 0x80000000u);
}
__device__ __forceinline__ float decf(unsigned u) {
    return (u & 0x80000000u) ? __uint_as_float(u & 0x7fffffffu) : __uint_as_float(~u);
}

// ---------------- launch A: init ∥ M = Wq^T @ Wk ----------------
__global__ void k_prep(float* __restrict__ outScore,
                       const float* __restrict__ Wq, const float* __restrict__ Wk) {
    __shared__ float sA[64][36];
    __shared__ float sB[64][72];
    int t = threadIdx.x;
    if (blockIdx.x < NBI) {
        int i = blockIdx.x * 256 + t;
        if (i < N_NODES) {
            g_segmax[i] = 0u;  g_segsum[i] = 0.f;
            g_segmax0[i] = 0u; g_segsum0[i] = 0.f;
            g_has[i] = 0; g_has0[i] = 0;
            outScore[i] = 0.f;
        }
        if (i < NQ) g_Qk0[i] = 0.f;
        if (i == 0) g_ncnt = 0;
        return;
    }
    int b = blockIdx.x - NBI;
    int ib = (b & 7) * 32, jb = (b >> 3) * 64;
    int tx = t & 15, ty = t >> 4;
    int r0 = ty * 2, c0 = tx * 4;
    float acc[2][4] = {};
    for (int kc = 0; kc < 256; kc += 64) {
        __syncthreads();
        {
            int ra = t >> 3, ca = (t & 7) * 4;
            for (int kk = ra; kk < 64; kk += 32)
                *(float4*)&sA[kk][ca] = *(const float4*)(Wq + (size_t)(kc + kk)*256 + ib + ca);
            int rbb = t >> 4, cbb = (t & 15) * 4;
            for (int kk = rbb; kk < 64; kk += 16)
                *(float4*)&sB[kk][cbb] = *(const float4*)(Wk + (size_t)(kc + kk)*256 + jb + cbb);
        }
        __syncthreads();
        #pragma unroll 8
        for (int k = 0; k < 64; k++) {
            float2 av = *(const float2*)&sA[k][r0];
            float4 bv = *(const float4*)&sB[k][c0];
            float a[2] = {av.x, av.y};
            float bb[4] = {bv.x, bv.y, bv.z, bv.w};
            #pragma unroll
            for (int ii = 0; ii < 2; ii++)
                #pragma unroll
                for (int jj = 0; jj < 4; jj++)
                    acc[ii][jj] = fmaf(a[ii], bb[jj], acc[ii][jj]);
        }
    }
    #pragma unroll
    for (int ii = 0; ii < 2; ii++)
        *(float4*)(g_M + (size_t)(ib + r0 + ii)*256 + jb + c0) =
            make_float4(acc[ii][0], acc[ii][1], acc[ii][2], acc[ii][3]);
}

__global__ void k_buildB(const float* __restrict__ W_lin) {
    int t = blockIdx.x * blockDim.x + threadIdx.x;
    if (t < 64*192) {
        int k = t / 192, c = t % 192;
        float v;
        if (c < 128) v = g_M[k*256 + c];
        else         v = g_M[(64 + (c-128))*256 + k];
        g_B1[t] = v;
    } else if (t < 64*192 + 64*64) {
        int t2 = t - 64*192; int k = t2 / 64, i = t2 % 64;
        g_B2[t2] = g_M[(64+i)*256 + (64+k)];
    } else if (t < 64*192 + 2*64*64) {
        int t3 = t - 64*192 - 64*64; int k = t3 / 64, i = t3 % 64;
        g_BL[t3] = W_lin[i*64 + k];
    } else if (t < 64*192 + 2*64*64 + 128*320) {
        int t4 = t - 64*192 - 2*64*64;
        int k = t4 / 320, c = t4 % 320;
        float v;
        if      (c < 64)  v = g_M[(128+k)*256 + c];
        else if (c < 128) v = g_M[(128+k)*256 + c] + g_M[c*256 + 128 + k];
        else if (c < 192) v = g_M[(c-128)*256 + 128 + k];
        else              v = g_M[(c-64)*256 + 128 + k];
        g_Bq[t4] = v;
    }
}

// ---------------- launch B: gemmN ∥ gemmQ(+k0) ----------------
extern __shared__ float smU[];

__device__ void gemmN_body(int bidN, const float* __restrict__ A) {
    float (*sAT)[68] = (float(*)[68])smU;
    float (*sB)[196] = (float(*)[196])(smU + 64*68);
    int t = threadIdx.x;
    int rb = bidN * 64;
    {
        int r = t >> 4, c4 = (t & 15) * 4;
        for (int rr = r; rr < 64; rr += 16) {
            float4 av = *(const float4*)(A + (size_t)(rb + rr)*64 + c4);
            sAT[c4+0][rr] = av.x; sAT[c4+1][rr] = av.y;
            sAT[c4+2][rr] = av.z; sAT[c4+3][rr] = av.w;
        }
        for (int kk = r; kk < 64; kk += 16) {
            #pragma unroll
            for (int co = 0; co < 3; co++)
                *(float4*)&sB[kk][c4 + co*64] = *(const float4*)(g_B1 + (size_t)kk*192 + c4 + co*64);
        }
    }
    __syncthreads();
    int tx = t & 31, ty = t >> 5;
    int r0 = ty * 8, c0 = tx * 6;
    u64 accd[4][3] = {};
    u64 acca[4][3] = {};
    #pragma unroll 4
    for (int k = 0; k < 64; k++) {
        u64 a2[4];
        #pragma unroll
        for (int p = 0; p < 4; p++) a2[p] = *(const u64*)&sAT[k][r0 + 2*p];
        u64 b2[3], bs[3];
        #pragma unroll
        for (int j = 0; j < 3; j++) {
            b2[j] = *(const u64*)&sB[k][c0 + 2*j];
            bs[j] = swp(b2[j]);
        }
        #pragma unroll
        for (int p = 0; p < 4; p++)
            #pragma unroll
            for (int j = 0; j < 3; j++) {
                fma2(accd[p][j], a2[p], b2[j]);
                fma2(acca[p][j], a2[p], bs[j]);
            }
    }
    #pragma unroll
    for (int p = 0; p < 4; p++) {
        float* C0 = g_nodeT + (size_t)(rb + r0 + 2*p)*192 + c0;
        float* C1 = C0 + 192;
        #pragma unroll
        for (int j = 0; j < 3; j++) {
            float2 d = upk(accd[p][j]), an = upk(acca[p][j]);
            *(u64*)(C0 + 2*j) = pk2(d.x, an.x);
            *(u64*)(C1 + 2*j) = pk2(an.y, d.y);
        }
    }
}

__device__ void gemmQ_body(int b, const float* __restrict__ qst, const float* __restrict__ qrl) {
    float (*sAT)[72] = (float(*)[72])smU;
    float (*sB)[72]  = (float(*)[72])(smU + 64*72);
    int t = threadIdx.x;
    int rb = (b & 63) * 64, cb = (b >> 6) * 64;
    int tx = t & 15, ty = t >> 4;
    int r0 = ty * 4, c0 = tx * 4;
    u64 acc2[4][2] = {};
    for (int kc = 0; kc < 128; kc += 64) {
        __syncthreads();
        {
            const float* Qsrc = (kc == 0) ? qst : qrl;
            int r = t >> 4, c4 = (t & 15) * 4;
            for (int rr = r; rr < 64; rr += 16) {
                float4 av = *(const float4*)(Qsrc + (size_t)(rb + rr)*64 + c4);
                sAT[c4+0][rr] = av.x; sAT[c4+1][rr] = av.y;
                sAT[c4+2][rr] = av.z; sAT[c4+3][rr] = av.w;
            }
            for (int kk = r; kk < 64; kk += 16)
                *(float4*)&sB[kk][c4] = *(const float4*)(g_Bq + (size_t)(kc + kk)*320 + cb + c4);
        }
        __syncthreads();
        #pragma unroll 8
        for (int k = 0; k < 64; k++) {
            float4 av = *(const float4*)&sAT[k][r0];
            u64 a2[4] = {pk2(av.x, av.x), pk2(av.y, av.y), pk2(av.z, av.z), pk2(av.w, av.w)};
            u64 b0 = *(const u64*)&sB[k][c0];
            u64 b1 = *(const u64*)&sB[k][c0 + 2];
            #pragma unroll
            for (int ii = 0; ii < 4; ii++) {
                fma2(acc2[ii][0], a2[ii], b0);
                fma2(acc2[ii][1], a2[ii], b1);
            }
        }
    }
    if (cb < 192) {
        #pragma unroll
        for (int ii = 0; ii < 4; ii++) {
            float* Cp = g_QT + (size_t)(rb + r0 + ii)*320 + cb + c0;
            *(u64*)Cp       = acc2[ii][0];
            *(u64*)(Cp + 2) = acc2[ii][1];
        }
    } else {
        const float* Qsrc2 = (cb == 192) ? qst : qrl;
        float qp[4];
        #pragma unroll
        for (int ii = 0; ii < 4; ii++) {
            float4 a = *(const float4*)(Qsrc2 + (size_t)(rb + r0 + ii)*64 + c0);
            float2 p0 = upk(acc2[ii][0]), p1 = upk(acc2[ii][1]);
            qp[ii] = p0.x*a.x + p0.y*a.y + p1.x*a.z + p1.y*a.w;
        }
        #pragma unroll
        for (int off = 8; off; off >>= 1)
            #pragma unroll
            for (int ii = 0; ii < 4; ii++)
                qp[ii] += __shfl_down_sync(~0u, qp[ii], off, 16);
        if (tx == 0) {
            #pragma unroll
            for (int ii = 0; ii < 4; ii++)
                atomicAdd(&g_Qk0[rb + r0 + ii], qp[ii]);
        }
    }
}

__global__ void k_uberB(const float* __restrict__ H,
                        const float* __restrict__ qst, const float* __restrict__ qrl) {
    int bid = blockIdx.x;
    if (bid < NB_N) gemmN_body(bid, H);
    else            gemmQ_body(bid - NB_N, qst, qrl);
}

// ---------------- quad: 256 edges/block, 4 tiles, 64 thr/tile, 8x8 pairs (1.0 B/FMA) ----------------
__global__ void __launch_bounds__(256, 2)
k_quad(const float* __restrict__ rel1, const float* __restrict__ rel0) {
    extern __shared__ float smQ[];
    int b = blockIdx.x;
    const float* rel; float* quadOut; int rb;
    if (b < E1N/256) { rel = rel1; quadOut = g_quad1; rb = b * 256; }
    else             { rel = rel0; quadOut = g_quad0; rb = (b - E1N/256) * 256; }
    float* sA = smQ;                                 // 4 tiles [64][68]
    float (*sB)[68] = (float(*)[68])(smQ + 4*64*68);
    int t = threadIdx.x;
    {
        int r = t >> 4, c4 = (t & 15) * 4;
        for (int rr = r; rr < 256; rr += 16) {
            float4 av = *(const float4*)(rel + (size_t)(rb + rr)*64 + c4);
            float* sAg = sA + (rr >> 6)*(64*68);
            int lrow = rr & 63;
            sAg[(c4+0)*68 + lrow] = av.x;
            sAg[(c4+1)*68 + lrow] = av.y;
            sAg[(c4+2)*68 + lrow] = av.z;
            sAg[(c4+3)*68 + lrow] = av.w;
        }
        for (int kk = r; kk < 64; kk += 16)
            *(float4*)&sB[kk][c4] = *(const float4*)(g_B2 + kk*64 + c4);
    }
    __syncthreads();
    int g = t >> 6, gt = t & 63;
    int tx = gt & 7, ty = gt >> 3;
    int r0 = ty * 8, c0 = tx * 8;
    const float (*sAg)[68] = (const float(*)[68])(sA + g*(64*68));
    u64 accd[4][4] = {};
    u64 acca[4][4] = {};
    #pragma unroll 4
    for (int k = 0; k < 64; k++) {
        u64 a2[4];
        #pragma unroll
        for (int p = 0; p < 4; p++) a2[p] = *(const u64*)&sAg[k][r0 + 2*p];
        u64 b2[4], bs[4];
        #pragma unroll
        for (int j = 0; j < 4; j++) {
            b2[j] = *(const u64*)&sB[k][c0 + 2*j];
            bs[j] = swp(b2[j]);
        }
        #pragma unroll
        for (int p = 0; p < 4; p++)
            #pragma unroll
            for (int j = 0; j < 4; j++) {
                fma2(accd[p][j], a2[p], b2[j]);
                fma2(acca[p][j], a2[p], bs[j]);
            }
    }
    // epilogue: row-dot Z against rel over this thread's 8 cols
    float qp[8];
    #pragma unroll
    for (int p = 0; p < 4; p++) {
        int erow = rb + g*64 + r0 + 2*p;
        float4 lo0 = *(const float4*)(rel + (size_t)erow*64 + c0);
        float4 lo1 = *(const float4*)(rel + (size_t)erow*64 + c0 + 4);
        float4 hi0 = *(const float4*)(rel + (size_t)(erow+1)*64 + c0);
        float4 hi1 = *(const float4*)(rel + (size_t)(erow+1)*64 + c0 + 4);
        float rlo[8] = {lo0.x,lo0.y,lo0.z,lo0.w,lo1.x,lo1.y,lo1.z,lo1.w};
        float rhi[8] = {hi0.x,hi0.y,hi0.z,hi0.w,hi1.x,hi1.y,hi1.z,hi1.w};
        float lo = 0.f, hi = 0.f;
        #pragma unroll
        for (int j = 0; j < 4; j++) {
            float2 d = upk(accd[p][j]), an = upk(acca[p][j]);
            lo = fmaf(d.x,  rlo[2*j],   lo);
            lo = fmaf(an.x, rlo[2*j+1], lo);
            hi = fmaf(an.y, rhi[2*j],   hi);
            hi = fmaf(d.y,  rhi[2*j+1], hi);
        }
        qp[2*p] = lo; qp[2*p+1] = hi;
    }
    #pragma unroll
    for (int off = 4; off; off >>= 1)
        #pragma unroll
        for (int r = 0; r < 8; r++)
            qp[r] += __shfl_down_sync(~0u, qp[r], off, 8);
    if (tx == 0) {
        #pragma unroll
        for (int r = 0; r < 8; r++)
            quadOut[rb + g*64 + r0 + r] = qp[r];
    }
}

// ---------------- logits: 16 lanes per edge, float4 loads ----------------
__global__ void k_logits1(const int* __restrict__ edges, const float* __restrict__ rel,
                          const float* __restrict__ H, const float* __restrict__ prior,
                          const float* __restrict__ gammaPtr) {
    __shared__ float sQ[192];
    __shared__ float sk0;
    int t = threadIdx.x;
    int q = blockIdx.x >> 2;
    if (t < 192) sQ[t] = g_QT[(size_t)q*320 + t];
    if (t == 192) sk0 = g_Qk0[q];
    __syncthreads();
    int e = blockIdx.x * 16 + (t >> 4);
    int sub = t & 15;
    int src = edges[e*8 + 6], dst = edges[e*8 + 7];
    float4 hs = *(const float4*)(H + (size_t)src*64 + sub*4);
    float4 hd = *(const float4*)(H + (size_t)dst*64 + sub*4);
    float4 P  = *(const float4*)(g_nodeT + (size_t)src*192 + sub*4);
    float4 U  = *(const float4*)(g_nodeT + (size_t)src*192 + 64 + sub*4);
    float4 Wd = *(const float4*)(g_nodeT + (size_t)dst*192 + 128 + sub*4);
    float4 rv = *(const float4*)(rel + (size_t)e*64 + sub*4);
    float4 dq = *(const float4*)(sQ + sub*4);
    float4 cq = *(const float4*)(sQ + 64 + sub*4);
    float4 vq = *(const float4*)(sQ + 128 + sub*4);
    float acc = (P.x + dq.x) * hd.x + (P.y + dq.y) * hd.y
              + (P.z + dq.z) * hd.z + (P.w + dq.w) * hd.w;
    acc = fmaf(rv.x, (U.x + cq.x + Wd.x), acc);
    acc = fmaf(rv.y, (U.y + cq.y + Wd.y), acc);
    acc = fmaf(rv.z, (U.z + cq.z + Wd.z), acc);
    acc = fmaf(rv.w, (U.w + cq.w + Wd.w), acc);
    acc = fmaf(vq.x, hs.x, acc);
    acc = fmaf(vq.y, hs.y, acc);
    acc = fmaf(vq.z, hs.z, acc);
    acc = fmaf(vq.w, hs.w, acc);
    #pragma unroll
    for (int o = 8; o; o >>= 1) acc += __shfl_xor_sync(~0u, acc, o, 16);
    if (sub == 0) {
        float l = acc + sk0 + g_quad1[e];
        l = fmaf(gammaPtr[0], prior[e], l);
        g_logit[e] = l;
        g_esrc[e] = src; g_edst[e] = dst;
        atomicMax(&g_segmax[src], encf(l));
    }
}

__global__ void k_logits0(const int* __restrict__ edges, const float* __restrict__ rel,
                          const float* __restrict__ H, int nE) {
    int e = blockIdx.x * 16 + (threadIdx.x >> 4);
    int sub = threadIdx.x & 15;
    if (e >= nE) return;
    int q = edges[e*8 + 0], src = edges[e*8 + 6], dst = edges[e*8 + 7];
    const float* Hs = g_has[src] ? (const float*)g_H1 : H;
    const float* Hd = g_has[dst] ? (const float*)g_H1 : H;
    float4 hs = *(const float4*)(Hs + (size_t)src*64 + sub*4);
    float4 hd = *(const float4*)(Hd + (size_t)dst*64 + sub*4);
    float4 P  = *(const float4*)(g_nodeT + (size_t)src*192 + sub*4);
    float4 U  = *(const float4*)(g_nodeT + (size_t)src*192 + 64 + sub*4);
    float4 Wd = *(const float4*)(g_nodeT + (size_t)dst*192 + 128 + sub*4);
    float4 rv = *(const float4*)(rel + (size_t)e*64 + sub*4);
    float4 dq = *(const float4*)(g_QT + (size_t)q*320 + sub*4);
    float4 cq = *(const float4*)(g_QT + (size_t)q*320 + 64 + sub*4);
    float4 vq = *(const float4*)(g_QT + (size_t)q*320 + 128 + sub*4);
    float acc = (P.x + dq.x) * hd.x + (P.y + dq.y) * hd.y
              + (P.z + dq.z) * hd.z + (P.w + dq.w) * hd.w;
    acc = fmaf(rv.x, (U.x + cq.x + Wd.x), acc);
    acc = fmaf(rv.y, (U.y + cq.y + Wd.y), acc);
    acc = fmaf(rv.z, (U.z + cq.z + Wd.z), acc);
    acc = fmaf(rv.w, (U.w + cq.w + Wd.w), acc);
    acc = fmaf(vq.x, hs.x, acc);
    acc = fmaf(vq.y, hs.y, acc);
    acc = fmaf(vq.z, hs.z, acc);
    acc = fmaf(vq.w, hs.w, acc);
    #pragma unroll
    for (int o = 8; o; o >>= 1) acc += __shfl_xor_sync(~0u, acc, o, 16);
    if (sub == 0) {
        float l = acc + g_Qk0[q] + g_quad0[e];
        g_logit[e] = l;
        g_esrc[e] = src; g_edst[e] = dst;
        atomicMax(&g_segmax0[src], encf(l));
    }
}

// exp + segment sum; stage0 also marks has0 + zeroes H2 row on first-set
__global__ void k_pass2(int stage0, int nE) {
    int e = blockIdx.x * blockDim.x + threadIdx.x;
    if (e >= nE) return;
    int src = g_esrc[e];
    if (!stage0) {
        float mx = decf(g_segmax[src]);
        float v = expf(g_logit[e] - mx);
        g_logit[e] = v;
        atomicAdd(&g_segsum[src], v);
    } else {
        float mx = decf(g_segmax0[src]);
        float v = expf(g_logit[e] - mx);
        g_logit[e] = v;
        atomicAdd(&g_segsum0[src], v);
        if (atomicExch(&g_has0[src], 1) == 0) {
            float4* hp = (float4*)(g_H2 + (size_t)src*64);
            #pragma unroll
            for (int c = 0; c < 16; c++) hp[c] = make_float4(0.f, 0.f, 0.f, 0.f);
        }
    }
}

// top-10 of 64 per query; builds chg list + zeroes H1 rows on first-set
__global__ void k_topk(const int* __restrict__ edges1, const float* __restrict__ score,
                       float* __restrict__ out) {
    int w = (blockIdx.x * blockDim.x + threadIdx.x) >> 5;
    int lane = threadIdx.x & 31;
    if (w >= NQ) return;
    int g0 = lane, g1 = lane + 32;
    int e0 = w*64 + g0, e1 = w*64 + g1;
    int s0 = g_esrc[e0], s1 = g_esrc[e1];
    float tr0 = g_logit[e0] / g_segsum[s0];
    float tr1 = g_logit[e1] / g_segsum[s1];
    float v0 = tr0 * score[s0];
    float v1 = tr1 * score[s1];
    int myG = 0; float myTr = 0.f;
    for (int k = 0; k < KSEL; k++) {
        float bv; int bg; float bt;
        if (v0 >= v1) { bv = v0; bg = g0; bt = tr0; }
        else          { bv = v1; bg = g1; bt = tr1; }
        for (int o = 16; o; o >>= 1) {
            float ov = __shfl_xor_sync(~0u, bv, o);
            int   og = __shfl_xor_sync(~0u, bg, o);
            float ot = __shfl_xor_sync(~0u, bt, o);
            if (ov > bv || (ov == bv && og < bg)) { bv = ov; bg = og; bt = ot; }
        }
        if (lane == k) { myG = bg; myTr = bt; }
        if (g0 == bg) v0 = -__int_as_float(0x7f800000);
        if (g1 == bg) v1 = -__int_as_float(0x7f800000);
    }
    if (lane < KSEL) {
        int orig = w*64 + myG;
        int oi = w*KSEL + lane;
        int src = g_esrc[orig], dst = g_edst[orig];
        g_psrc[oi] = src; g_pdst[oi] = dst; g_ptrans[oi] = myTr;
        if (atomicExch(&g_has[src], 1) == 0) {
            int idx = atomicAdd(&g_ncnt, 1);
            g_chg[idx] = src;
            float4* hp = (float4*)(g_H1 + (size_t)src*64);
            #pragma unroll
            for (int c = 0; c < 16; c++) hp[c] = make_float4(0.f, 0.f, 0.f, 0.f);
        }
        atomicAdd(out + dst, myTr * score[src]);
        float* pe = out + OFF_PE + (size_t)oi*8;
        for (int c = 0; c < 8; c++) pe[c] = (float)edges1[orig*8 + c];
        out[OFF_OI + oi] = (float)orig;
    }
}

__global__ void k_scatter1(const float* __restrict__ H) {
    int w = (blockIdx.x * blockDim.x + threadIdx.x) >> 5;
    int lane = threadIdx.x & 31;
    if (w >= NQ*KSEL) return;
    int src = g_psrc[w], dst = g_pdst[w];
    float t = g_ptrans[w];
    float2 hv = ((const float2*)(H + (size_t)dst*64))[lane];
    red2(&g_H1[(size_t)src*64 + 2*lane], t * hv.x, t * hv.y);
}

// delta nodeT: 64 gathered rows x 192 cols per block, 8x6 pairs
__global__ void k_dgemm(const float* __restrict__ Hold) {
    extern __shared__ float smD[];
    float (*sAT)[68] = (float(*)[68])smD;
    float (*sB)[196] = (float(*)[196])(smD + 64*68);
    __shared__ int snode[64];
    int cnt = g_ncnt;
    int rb = blockIdx.x * 64;
    if (rb >= cnt) return;
    int t = threadIdx.x;
    if (t < 64) snode[t] = (rb + t < cnt) ? g_chg[rb + t] : -1;
    __syncthreads();
    {
        int r = t >> 4, c4 = (t & 15) * 4;
        for (int rr = r; rr < 64; rr += 16) {
            int node = snode[rr];
            float4 av = make_float4(0.f, 0.f, 0.f, 0.f);
            if (node >= 0) {
                float4 a = *(const float4*)(g_H1 + (size_t)node*64 + c4);
                float4 b = *(const float4*)(Hold + (size_t)node*64 + c4);
                av = make_float4(a.x - b.x, a.y - b.y, a.z - b.z, a.w - b.w);
            }
            sAT[c4+0][rr] = av.x; sAT[c4+1][rr] = av.y;
            sAT[c4+2][rr] = av.z; sAT[c4+3][rr] = av.w;
        }
        for (int kk = r; kk < 64; kk += 16) {
            #pragma unroll
            for (int co = 0; co < 3; co++)
                *(float4*)&sB[kk][c4 + co*64] = *(const float4*)(g_B1 + (size_t)kk*192 + c4 + co*64);
        }
    }
    __syncthreads();
    int tx = t & 31, ty = t >> 5;
    int r0 = ty * 8, c0 = tx * 6;
    u64 accd[4][3] = {};
    u64 acca[4][3] = {};
    #pragma unroll 4
    for (int k = 0; k < 64; k++) {
        u64 a2[4];
        #pragma unroll
        for (int p = 0; p < 4; p++) a2[p] = *(const u64*)&sAT[k][r0 + 2*p];
        u64 b2[3], bs[3];
        #pragma unroll
        for (int j = 0; j < 3; j++) {
            b2[j] = *(const u64*)&sB[k][c0 + 2*j];
            bs[j] = swp(b2[j]);
        }
        #pragma unroll
        for (int p = 0; p < 4; p++)
            #pragma unroll
            for (int j = 0; j < 3; j++) {
                fma2(accd[p][j], a2[p], b2[j]);
                fma2(acca[p][j], a2[p], bs[j]);
            }
    }
    #pragma unroll
    for (int p = 0; p < 4; p++) {
        int n0 = snode[r0 + 2*p], n1 = snode[r0 + 2*p + 1];
        #pragma unroll
        for (int j = 0; j < 3; j++) {
            float2 d = upk(accd[p][j]), an = upk(acca[p][j]);
            if (n0 >= 0) {
                float* C0 = g_nodeT + (size_t)n0*192 + c0 + 2*j;
                float2 co = upk(*(u64*)C0);
                *(u64*)C0 = pk2(co.x + d.x, co.y + an.x);
            }
            if (n1 >= 0) {
                float* C1 = g_nodeT + (size_t)n1*192 + c0 + 2*j;
                float2 co = upk(*(u64*)C1);
                *(u64*)C1 = pk2(co.x + an.y, co.y + d.y);
            }
        }
    }
}

__global__ void k_scatter0(const float* __restrict__ H) {
    int w = (blockIdx.x * blockDim.x + threadIdx.x) >> 5;
    int lane = threadIdx.x & 31;
    if (w >= E0N) return;
    int src = g_esrc[w], dst = g_edst[w];
    float t = g_logit[w] / g_segsum0[src];
    const float* Hd = g_has[dst] ? (const float*)g_H1 : H;
    float2 hv = ((const float2*)(Hd + (size_t)dst*64))[lane];
    red2(&g_H2[(size_t)src*64 + 2*lane], t * hv.x, t * hv.y);
}

// final GEMM: 128 rows/block (2 tiles), 64 thr/tile, 8x8 pairs, virtual A select
__global__ void k_gemmF(const float* __restrict__ H, float* __restrict__ C,
                        const float* __restrict__ bias) {
    extern __shared__ float smF[];
    float* sA = smF;
    float (*sB)[68] = (float(*)[68])(smF + 2*64*68);
    int t = threadIdx.x;
    int rb = blockIdx.x * 128;
    {
        int r = t >> 4, c4 = (t & 15) * 4;
        for (int rr = r; rr < 128; rr += 8) {
            int node = rb + rr; if (node >= N_NODES) node = N_NODES - 1;
            const float* Ap = g_has0[node] ? (const float*)g_H2
                             : (g_has[node] ? (const float*)g_H1 : H);
            float4 av = *(const float4*)(Ap + (size_t)node*64 + c4);
            float* sAg = sA + (rr >> 6)*(64*68);
            int lrow = rr & 63;
            sAg[(c4+0)*68 + lrow] = av.x;
            sAg[(c4+1)*68 + lrow] = av.y;
            sAg[(c4+2)*68 + lrow] = av.z;
            sAg[(c4+3)*68 + lrow] = av.w;
        }
        for (int kk = r; kk < 64; kk += 8)
            *(float4*)&sB[kk][c4] = *(const float4*)(g_BL + kk*64 + c4);
    }
    __syncthreads();
    int g = t >> 6, gt = t & 63;
    int tx = gt & 7, ty = gt >> 3;
    int r0 = ty * 8, c0 = tx * 8;
    const float (*sAg)[68] = (const float(*)[68])(sA + g*(64*68));
    u64 accd[4][4] = {};
    u64 acca[4][4] = {};
    #pragma unroll 4
    for (int k = 0; k < 64; k++) {
        u64 a2[4];
        #pragma unroll
        for (int p = 0; p < 4; p++) a2[p] = *(const u64*)&sAg[k][r0 + 2*p];
        u64 b2[4], bs[4];
        #pragma unroll
        for (int j = 0; j < 4; j++) {
            b2[j] = *(const u64*)&sB[k][c0 + 2*j];
            bs[j] = swp(b2[j]);
        }
        #pragma unroll
        for (int p = 0; p < 4; p++)
            #pragma unroll
            for (int j = 0; j < 4; j++) {
                fma2(accd[p][j], a2[p], b2[j]);
                fma2(acca[p][j], a2[p], bs[j]);
            }
    }
    float bl[8];
    #pragma unroll
    for (int j = 0; j < 8; j++) bl[j] = bias[c0 + j];
    #pragma unroll
    for (int p = 0; p < 4; p++) {
        int row0 = rb + g*64 + r0 + 2*p;
        float o0[8], o1[8];
        #pragma unroll
        for (int j = 0; j < 4; j++) {
            float2 d = upk(accd[p][j]), an = upk(acca[p][j]);
            o0[2*j] = d.x;  o0[2*j+1] = an.x;
            o1[2*j] = an.y; o1[2*j+1] = d.y;
        }
        #pragma unroll
        for (int j = 0; j < 8; j++) {
            float x = o0[j] + bl[j]; o0[j] = x >= 0.f ? x : 0.01f * x;
            float y = o1[j] + bl[j]; o1[j] = y >= 0.f ? y : 0.01f * y;
        }
        if (row0 < N_NODES) {
            float* Cp = C + (size_t)row0*64 + c0;
            *(float4*)Cp     = make_float4(o0[0], o0[1], o0[2], o0[3]);
            *(float4*)(Cp+4) = make_float4(o0[4], o0[5], o0[6], o0[7]);
        }
        if (row0 + 1 < N_NODES) {
            float* Cp = C + (size_t)(row0+1)*64 + c0;
            *(float4*)Cp     = make_float4(o1[0], o1[1], o1[2], o1[3]);
            *(float4*)(Cp+4) = make_float4(o1[4], o1[5], o1[6], o1[7]);
        }
    }
}

// ---------------- launch ----------------
extern "C" void kernel_launch(void* const* d_in, const int* in_sizes, int n_in,
                              void* d_out, int out_size) {
    const float* score = (const float*)d_in[0];
    const float* H     = (const float*)d_in[1];
    const float* rel0  = (const float*)d_in[2];
    const float* rel1  = (const float*)d_in[3];
    const float* prior = (const float*)d_in[4];
    const float* qst   = (const float*)d_in[5];
    const float* qrl   = (const float*)d_in[6];
    const float* Wq    = (const float*)d_in[7];
    const float* Wk    = (const float*)d_in[8];
    const float* Wlin  = (const float*)d_in[9];
    const float* blin  = (const float*)d_in[10];
    const float* gamma = (const float*)d_in[11];
    const int*   e0    = (const int*)d_in[12];
    const int*   e1    = (const int*)d_in[13];
    float* out = (float*)d_out;

    const int USMEM = (64*68 + 64*196) * 4;   // 67584 B
    const int QSMEM = 5*64*68*4;              // 87040 B
    const int FSMEM = 3*64*68*4;              // 52224 B
    cudaFuncSetAttribute(k_uberB, cudaFuncAttributeMaxDynamicSharedMemorySize, USMEM);
    cudaFuncSetAttribute(k_quad,  cudaFuncAttributeMaxDynamicSharedMemorySize, QSMEM);
    cudaFuncSetAttribute(k_dgemm, cudaFuncAttributeMaxDynamicSharedMemorySize, USMEM);
    cudaFuncSetAttribute(k_gemmF, cudaFuncAttributeMaxDynamicSharedMemorySize, FSMEM);

    k_prep<<<NBI + 32, 256>>>(out, Wq, Wk);
    k_buildB<<<(64*192 + 2*64*64 + 128*320 + 255)/256, 256>>>(Wlin);
    k_uberB<<<NB_N + NB_QT, 256, USMEM>>>(H, qst, qrl);
    k_quad<<<NB_Q2, 256, QSMEM>>>(rel1, rel0);

    // ---- stage 1 ----
    k_logits1<<<E1N/16, 256>>>(e1, rel1, H, prior, gamma);
    k_pass2<<<E1N/256, 256>>>(0, E1N);
    k_topk<<<NQ/8, 256>>>(e1, score, out);
    k_scatter1<<<(NQ*KSEL)/8, 256>>>(H);

    // ---- stage 0 ----
    k_dgemm<<<(NQ*KSEL)/64, 256, USMEM>>>(H);
    k_logits0<<<E0N/16, 256>>>(e0, rel0, H, E0N);
    k_pass2<<<E0N/256, 256>>>(1, E0N);
    k_scatter0<<<E0N/8, 256>>>(H);

    // ---- final ----
    k_gemmF<<<(N_NODES + 127)/128, 128, FSMEM>>>(H, out + OFF_REPR, blin);
}

// round 17
// speedup vs baseline: 1.0825x; 1.0825x over previous
#include <cuda_runtime.h>
#include <cstdint>

#define N_NODES 200000
#define DIM 64
#define NQ 4096
#define E1N 262144
#define E0N 131072
#define KSEL 10

#define OFF_REPR  (N_NODES)
#define OFF_PE    (N_NODES + N_NODES*DIM)
#define OFF_OI    (OFF_PE + NQ*KSEL*8)

#define NBI   ((N_NODES + 255)/256)
#define NB_N  (N_NODES/64)
#define NB_QT ((NQ/64)*5)
#define NB_QD ((E1N + E0N)/128)

typedef unsigned long long u64;

__device__ __forceinline__ u64 pk2(float lo, float hi) {
    u64 r; asm("mov.b64 %0, {%1, %2};" : "=l"(r) : "f"(lo), "f"(hi)); return r;
}
__device__ __forceinline__ void fma2(u64& d, u64 a, u64 b) {
    asm("fma.rn.f32x2 %0, %1, %2, %0;" : "+l"(d) : "l"(a), "l"(b));
}
__device__ __forceinline__ float2 upk(u64 v) {
    float2 r; asm("mov.b64 {%0, %1}, %2;" : "=f"(r.x), "=f"(r.y) : "l"(v)); return r;
}
__device__ __forceinline__ u64 swp(u64 v) {
    float2 f = upk(v); return pk2(f.y, f.x);
}
__device__ __forceinline__ void red2(float* p, float x, float y) {
    asm volatile("red.global.add.v2.f32 [%0], {%1, %2};" :: "l"(p), "f"(x), "f"(y) : "memory");
}

// ---------------- scratch ----------------
__device__ float    g_M [256*256];
__device__ float    g_B1[64*192];
__device__ float    g_B2[64*64];
__device__ float    g_BL[64*64];
__device__ float    g_Bq[128*320];
__device__ float    g_QT[(size_t)NQ*320];
__device__ float    g_Qk0[NQ];
__device__ float    g_nodeT[(size_t)N_NODES*192];
__device__ float    g_quad1[E1N];
__device__ float    g_quad0[E0N];
__device__ float    g_logit[E1N];
__device__ int      g_esrc[E1N];
__device__ int      g_edst[E1N];
__device__ unsigned g_segmax [N_NODES];
__device__ float    g_segsum [N_NODES];
__device__ unsigned g_segmax0[N_NODES];
__device__ float    g_segsum0[N_NODES];
__device__ int      g_has [N_NODES];
__device__ int      g_has0[N_NODES];
__device__ float    g_H1[(size_t)N_NODES*DIM];
__device__ float    g_H2[(size_t)N_NODES*DIM];
__device__ int      g_psrc[NQ*KSEL];
__device__ int      g_pdst[NQ*KSEL];
__device__ float    g_ptrans[NQ*KSEL];
__device__ int      g_chg[NQ*KSEL];
__device__ int      g_ncnt;

__device__ __forceinline__ unsigned encf(float f) {
    unsigned u = __float_as_uint(f);
    return (u & 0x80000000u) ? ~u : (u | 0x80000000u);
}
__device__ __forceinline__ float decf(unsigned u) {
    return (u & 0x80000000u) ? __uint_as_float(u & 0x7fffffffu) : __uint_as_float(~u);
}

// ---------------- launch A: init ∥ M = Wq^T @ Wk ----------------
__global__ void k_prep(float* __restrict__ outScore,
                       const float* __restrict__ Wq, const float* __restrict__ Wk) {
    __shared__ float sA[64][36];
    __shared__ float sB[64][72];
    int t = threadIdx.x;
    if (blockIdx.x < NBI) {
        int i = blockIdx.x * 256 + t;
        if (i < N_NODES) {
            g_segmax[i] = 0u;  g_segsum[i] = 0.f;
            g_segmax0[i] = 0u; g_segsum0[i] = 0.f;
            g_has[i] = 0; g_has0[i] = 0;
            outScore[i] = 0.f;
        }
        if (i < NQ) g_Qk0[i] = 0.f;
        if (i == 0) g_ncnt = 0;
        return;
    }
    int b = blockIdx.x - NBI;
    int ib = (b & 7) * 32, jb = (b >> 3) * 64;
    int tx = t & 15, ty = t >> 4;
    int r0 = ty * 2, c0 = tx * 4;
    float acc[2][4] = {};
    for (int kc = 0; kc < 256; kc += 64) {
        __syncthreads();
        {
            int ra = t >> 3, ca = (t & 7) * 4;
            for (int kk = ra; kk < 64; kk += 32)
                *(float4*)&sA[kk][ca] = *(const float4*)(Wq + (size_t)(kc + kk)*256 + ib + ca);
            int rbb = t >> 4, cbb = (t & 15) * 4;
            for (int kk = rbb; kk < 64; kk += 16)
                *(float4*)&sB[kk][cbb] = *(const float4*)(Wk + (size_t)(kc + kk)*256 + jb + cbb);
        }
        __syncthreads();
        #pragma unroll 8
        for (int k = 0; k < 64; k++) {
            float2 av = *(const float2*)&sA[k][r0];
            float4 bv = *(const float4*)&sB[k][c0];
            float a[2] = {av.x, av.y};
            float bb[4] = {bv.x, bv.y, bv.z, bv.w};
            #pragma unroll
            for (int ii = 0; ii < 2; ii++)
                #pragma unroll
                for (int jj = 0; jj < 4; jj++)
                    acc[ii][jj] = fmaf(a[ii], bb[jj], acc[ii][jj]);
        }
    }
    #pragma unroll
    for (int ii = 0; ii < 2; ii++)
        *(float4*)(g_M + (size_t)(ib + r0 + ii)*256 + jb + c0) =
            make_float4(acc[ii][0], acc[ii][1], acc[ii][2], acc[ii][3]);
}

__global__ void k_buildB(const float* __restrict__ W_lin) {
    int t = blockIdx.x * blockDim.x + threadIdx.x;
    if (t < 64*192) {
        int k = t / 192, c = t % 192;
        float v;
        if (c < 128) v = g_M[k*256 + c];
        else         v = g_M[(64 + (c-128))*256 + k];
        g_B1[t] = v;
    } else if (t < 64*192 + 64*64) {
        int t2 = t - 64*192; int k = t2 / 64, i = t2 % 64;
        g_B2[t2] = g_M[(64+i)*256 + (64+k)];
    } else if (t < 64*192 + 2*64*64) {
        int t3 = t - 64*192 - 64*64; int k = t3 / 64, i = t3 % 64;
        g_BL[t3] = W_lin[i*64 + k];
    } else if (t < 64*192 + 2*64*64 + 128*320) {
        int t4 = t - 64*192 - 2*64*64;
        int k = t4 / 320, c = t4 % 320;
        float v;
        if      (c < 64)  v = g_M[(128+k)*256 + c];
        else if (c < 128) v = g_M[(128+k)*256 + c] + g_M[c*256 + 128 + k];
        else if (c < 192) v = g_M[(c-128)*256 + 128 + k];
        else              v = g_M[(c-64)*256 + 128 + k];
        g_Bq[t4] = v;
    }
}

// ---------------- launch B: gemmN ∥ gemmQ(+k0) ∥ quadBoth (2x2 FFMA2 pairs) ----------------
extern __shared__ float smU[];

__device__ void gemmN_body(int bidN, const float* __restrict__ A) {
    float (*sAT)[68] = (float(*)[68])smU;
    float (*sB)[196] = (float(*)[196])(smU + 64*68);
    int t = threadIdx.x;
    int rb = bidN * 64;
    {
        int r = t >> 4, c4 = (t & 15) * 4;
        for (int rr = r; rr < 64; rr += 16) {
            float4 av = *(const float4*)(A + (size_t)(rb + rr)*64 + c4);
            sAT[c4+0][rr] = av.x; sAT[c4+1][rr] = av.y;
            sAT[c4+2][rr] = av.z; sAT[c4+3][rr] = av.w;
        }
        for (int kk = r; kk < 64; kk += 16) {
            #pragma unroll
            for (int co = 0; co < 3; co++)
                *(float4*)&sB[kk][c4 + co*64] = *(const float4*)(g_B1 + (size_t)kk*192 + c4 + co*64);
        }
    }
    __syncthreads();
    int tx = t & 31, ty = t >> 5;
    int r0 = ty * 8, c0 = tx * 6;
    u64 accd[4][3] = {};
    u64 acca[4][3] = {};
    #pragma unroll 4
    for (int k = 0; k < 64; k++) {
        u64 a2[4];
        #pragma unroll
        for (int p = 0; p < 4; p++) a2[p] = *(const u64*)&sAT[k][r0 + 2*p];
        u64 b2[3], bs[3];
        #pragma unroll
        for (int j = 0; j < 3; j++) {
            b2[j] = *(const u64*)&sB[k][c0 + 2*j];
            bs[j] = swp(b2[j]);
        }
        #pragma unroll
        for (int p = 0; p < 4; p++)
            #pragma unroll
            for (int j = 0; j < 3; j++) {
                fma2(accd[p][j], a2[p], b2[j]);
                fma2(acca[p][j], a2[p], bs[j]);
            }
    }
    #pragma unroll
    for (int p = 0; p < 4; p++) {
        float* C0 = g_nodeT + (size_t)(rb + r0 + 2*p)*192 + c0;
        float* C1 = C0 + 192;
        #pragma unroll
        for (int j = 0; j < 3; j++) {
            float2 d = upk(accd[p][j]), an = upk(acca[p][j]);
            *(u64*)(C0 + 2*j) = pk2(d.x, an.x);
            *(u64*)(C1 + 2*j) = pk2(an.y, d.y);
        }
    }
}

__device__ void gemmQ_body(int b, const float* __restrict__ qst, const float* __restrict__ qrl) {
    float (*sAT)[72] = (float(*)[72])smU;
    float (*sB)[72]  = (float(*)[72])(smU + 64*72);
    int t = threadIdx.x;
    int rb = (b & 63) * 64, cb = (b >> 6) * 64;
    int tx = t & 15, ty = t >> 4;
    int r0 = ty * 4, c0 = tx * 4;
    u64 acc2[4][2] = {};
    for (int kc = 0; kc < 128; kc += 64) {
        __syncthreads();
        {
            const float* Qsrc = (kc == 0) ? qst : qrl;
            int r = t >> 4, c4 = (t & 15) * 4;
            for (int rr = r; rr < 64; rr += 16) {
                float4 av = *(const float4*)(Qsrc + (size_t)(rb + rr)*64 + c4);
                sAT[c4+0][rr] = av.x; sAT[c4+1][rr] = av.y;
                sAT[c4+2][rr] = av.z; sAT[c4+3][rr] = av.w;
            }
            for (int kk = r; kk < 64; kk += 16)
                *(float4*)&sB[kk][c4] = *(const float4*)(g_Bq + (size_t)(kc + kk)*320 + cb + c4);
        }
        __syncthreads();
        #pragma unroll 8
        for (int k = 0; k < 64; k++) {
            float4 av = *(const float4*)&sAT[k][r0];
            u64 a2[4] = {pk2(av.x, av.x), pk2(av.y, av.y), pk2(av.z, av.z), pk2(av.w, av.w)};
            u64 b0 = *(const u64*)&sB[k][c0];
            u64 b1 = *(const u64*)&sB[k][c0 + 2];
            #pragma unroll
            for (int ii = 0; ii < 4; ii++) {
                fma2(acc2[ii][0], a2[ii], b0);
                fma2(acc2[ii][1], a2[ii], b1);
            }
        }
    }
    if (cb < 192) {
        #pragma unroll
        for (int ii = 0; ii < 4; ii++) {
            float* Cp = g_QT + (size_t)(rb + r0 + ii)*320 + cb + c0;
            *(u64*)Cp       = acc2[ii][0];
            *(u64*)(Cp + 2) = acc2[ii][1];
        }
    } else {
        const float* Qsrc2 = (cb == 192) ? qst : qrl;
        float qp[4];
        #pragma unroll
        for (int ii = 0; ii < 4; ii++) {
            float4 a = *(const float4*)(Qsrc2 + (size_t)(rb + r0 + ii)*64 + c0);
            float2 p0 = upk(acc2[ii][0]), p1 = upk(acc2[ii][1]);
            qp[ii] = p0.x*a.x + p0.y*a.y + p1.x*a.z + p1.y*a.w;
        }
        #pragma unroll
        for (int off = 8; off; off >>= 1)
            #pragma unroll
            for (int ii = 0; ii < 4; ii++)
                qp[ii] += __shfl_down_sync(~0u, qp[ii], off, 16);
        if (tx == 0) {
            #pragma unroll
            for (int ii = 0; ii < 4; ii++)
                atomicAdd(&g_Qk0[rb + r0 + ii], qp[ii]);
        }
    }
}

__device__ void quad_body(int b, const float* __restrict__ rel1, const float* __restrict__ rel0) {
    const float* rel; float* quadOut; int rb;
    if (b < E1N/128) { rel = rel1; quadOut = g_quad1; rb = b * 128; }
    else             { rel = rel0; quadOut = g_quad0; rb = (b - E1N/128) * 128; }
    float* sA = smU;
    float (*sB)[68] = (float(*)[68])(smU + 2*64*68);
    int t = threadIdx.x;
    {
        int r = t >> 4, c4 = (t & 15) * 4;
        for (int rr = r; rr < 128; rr += 16) {
            float4 av = *(const float4*)(rel + (size_t)(rb + rr)*64 + c4);
            float* sAg = sA + (rr >> 6)*(64*68);
            int lrow = rr & 63;
            sAg[(c4+0)*68 + lrow] = av.x;
            sAg[(c4+1)*68 + lrow] = av.y;
            sAg[(c4+2)*68 + lrow] = av.z;
            sAg[(c4+3)*68 + lrow] = av.w;
        }
        for (int kk = r; kk < 64; kk += 16)
            *(float4*)&sB[kk][c4] = *(const float4*)(g_B2 + kk*64 + c4);
    }
    __syncthreads();
    int g = t >> 7, gt = t & 127;
    int tx = gt & 15, ty = gt >> 4;
    int r0 = ty * 8, c0 = tx * 4;
    const float (*sAg)[68] = (const float(*)[68])(sA + g*(64*68));
    u64 accd[4][2] = {};
    u64 acca[4][2] = {};
    #pragma unroll 4
    for (int k = 0; k < 64; k++) {
        u64 a2[4];
        #pragma unroll
        for (int p = 0; p < 4; p++) a2[p] = *(const u64*)&sAg[k][r0 + 2*p];
        u64 b0 = *(const u64*)&sB[k][c0];
        u64 b1 = *(const u64*)&sB[k][c0 + 2];
        u64 s0 = swp(b0), s1 = swp(b1);
        #pragma unroll
        for (int p = 0; p < 4; p++) {
            fma2(accd[p][0], a2[p], b0);
            fma2(acca[p][0], a2[p], s0);
            fma2(accd[p][1], a2[p], b1);
            fma2(acca[p][1], a2[p], s1);
        }
    }
    float qp[8];
    #pragma unroll
    for (int p = 0; p < 4; p++) {
        int erow = rb + g*64 + r0 + 2*p;
        float4 aLo = *(const float4*)(rel + (size_t)erow*64 + c0);
        float4 aHi = *(const float4*)(rel + (size_t)(erow+1)*64 + c0);
        float2 d0 = upk(accd[p][0]), a0 = upk(acca[p][0]);
        float2 d1 = upk(accd[p][1]), a1 = upk(acca[p][1]);
        qp[2*p]   = d0.x*aLo.x + a0.x*aLo.y + d1.x*aLo.z + a1.x*aLo.w;
        qp[2*p+1] = a0.y*aHi.x + d0.y*aHi.y + a1.y*aHi.z + d1.y*aHi.w;
    }
    #pragma unroll
    for (int off = 8; off; off >>= 1)
        #pragma unroll
        for (int r = 0; r < 8; r++)
            qp[r] += __shfl_down_sync(~0u, qp[r], off, 16);
    if (tx == 0) {
        #pragma unroll
        for (int r = 0; r < 8; r++)
            quadOut[rb + g*64 + r0 + r] = qp[r];
    }
}

__global__ void k_uberB(const float* __restrict__ H,
                        const float* __restrict__ rel1, const float* __restrict__ rel0,
                        const float* __restrict__ qst,  const float* __restrict__ qrl) {
    int bid = blockIdx.x;
    if (bid < NB_N)              gemmN_body(bid, H);
    else if (bid < NB_N + NB_QT) gemmQ_body(bid - NB_N, qst, qrl);
    else                         quad_body(bid - NB_N - NB_QT, rel1, rel0);
}

// ---------------- logits: 16 lanes per edge, float4 loads ----------------
__global__ void k_logits1(const int* __restrict__ edges, const float* __restrict__ rel,
                          const float* __restrict__ H, const float* __restrict__ prior,
                          const float* __restrict__ gammaPtr) {
    __shared__ float sQ[192];
    __shared__ float sk0;
    int t = threadIdx.x;
    int q = blockIdx.x >> 2;
    if (t < 192) sQ[t] = g_QT[(size_t)q*320 + t];
    if (t == 192) sk0 = g_Qk0[q];
    __syncthreads();
    int e = blockIdx.x * 16 + (t >> 4);
    int sub = t & 15;
    int src = edges[e*8 + 6], dst = edges[e*8 + 7];
    float4 hs = *(const float4*)(H + (size_t)src*64 + sub*4);
    float4 hd = *(const float4*)(H + (size_t)dst*64 + sub*4);
    float4 P  = *(const float4*)(g_nodeT + (size_t)src*192 + sub*4);
    float4 U  = *(const float4*)(g_nodeT + (size_t)src*192 + 64 + sub*4);
    float4 Wd = *(const float4*)(g_nodeT + (size_t)dst*192 + 128 + sub*4);
    float4 rv = *(const float4*)(rel + (size_t)e*64 + sub*4);
    float4 dq = *(const float4*)(sQ + sub*4);
    float4 cq = *(const float4*)(sQ + 64 + sub*4);
    float4 vq = *(const float4*)(sQ + 128 + sub*4);
    float acc = (P.x + dq.x) * hd.x + (P.y + dq.y) * hd.y
              + (P.z + dq.z) * hd.z + (P.w + dq.w) * hd.w;
    acc = fmaf(rv.x, (U.x + cq.x + Wd.x), acc);
    acc = fmaf(rv.y, (U.y + cq.y + Wd.y), acc);
    acc = fmaf(rv.z, (U.z + cq.z + Wd.z), acc);
    acc = fmaf(rv.w, (U.w + cq.w + Wd.w), acc);
    acc = fmaf(vq.x, hs.x, acc);
    acc = fmaf(vq.y, hs.y, acc);
    acc = fmaf(vq.z, hs.z, acc);
    acc = fmaf(vq.w, hs.w, acc);
    #pragma unroll
    for (int o = 8; o; o >>= 1) acc += __shfl_xor_sync(~0u, acc, o, 16);
    if (sub == 0) {
        float l = acc + sk0 + g_quad1[e];
        l = fmaf(gammaPtr[0], prior[e], l);
        g_logit[e] = l;
        g_esrc[e] = src; g_edst[e] = dst;
        atomicMax(&g_segmax[src], encf(l));
    }
}

__global__ void k_logits0(const int* __restrict__ edges, const float* __restrict__ rel,
                          const float* __restrict__ H, int nE) {
    int e = blockIdx.x * 16 + (threadIdx.x >> 4);
    int sub = threadIdx.x & 15;
    if (e >= nE) return;
    int q = edges[e*8 + 0], src = edges[e*8 + 6], dst = edges[e*8 + 7];
    const float* Hs = g_has[src] ? (const float*)g_H1 : H;
    const float* Hd = g_has[dst] ? (const float*)g_H1 : H;
    float4 hs = *(const float4*)(Hs + (size_t)src*64 + sub*4);
    float4 hd = *(const float4*)(Hd + (size_t)dst*64 + sub*4);
    float4 P  = *(const float4*)(g_nodeT + (size_t)src*192 + sub*4);
    float4 U  = *(const float4*)(g_nodeT + (size_t)src*192 + 64 + sub*4);
    float4 Wd = *(const float4*)(g_nodeT + (size_t)dst*192 + 128 + sub*4);
    float4 rv = *(const float4*)(rel + (size_t)e*64 + sub*4);
    float4 dq = *(const float4*)(g_QT + (size_t)q*320 + sub*4);
    float4 cq = *(const float4*)(g_QT + (size_t)q*320 + 64 + sub*4);
    float4 vq = *(const float4*)(g_QT + (size_t)q*320 + 128 + sub*4);
    float acc = (P.x + dq.x) * hd.x + (P.y + dq.y) * hd.y
              + (P.z + dq.z) * hd.z + (P.w + dq.w) * hd.w;
    acc = fmaf(rv.x, (U.x + cq.x + Wd.x), acc);
    acc = fmaf(rv.y, (U.y + cq.y + Wd.y), acc);
    acc = fmaf(rv.z, (U.z + cq.z + Wd.z), acc);
    acc = fmaf(rv.w, (U.w + cq.w + Wd.w), acc);
    acc = fmaf(vq.x, hs.x, acc);
    acc = fmaf(vq.y, hs.y, acc);
    acc = fmaf(vq.z, hs.z, acc);
    acc = fmaf(vq.w, hs.w, acc);
    #pragma unroll
    for (int o = 8; o; o >>= 1) acc += __shfl_xor_sync(~0u, acc, o, 16);
    if (sub == 0) {
        float l = acc + g_Qk0[q] + g_quad0[e];
        g_logit[e] = l;
        g_esrc[e] = src; g_edst[e] = dst;
        atomicMax(&g_segmax0[src], encf(l));
    }
}

// exp + segment sum; stage0 also marks has0 + zeroes H2 row on first-set
__global__ void k_pass2(int stage0, int nE) {
    int e = blockIdx.x * blockDim.x + threadIdx.x;
    if (e >= nE) return;
    int src = g_esrc[e];
    if (!stage0) {
        float mx = decf(g_segmax[src]);
        float v = expf(g_logit[e] - mx);
        g_logit[e] = v;
        atomicAdd(&g_segsum[src], v);
    } else {
        float mx = decf(g_segmax0[src]);
        float v = expf(g_logit[e] - mx);
        g_logit[e] = v;
        atomicAdd(&g_segsum0[src], v);
        if (atomicExch(&g_has0[src], 1) == 0) {
            float4* hp = (float4*)(g_H2 + (size_t)src*64);
            #pragma unroll
            for (int c = 0; c < 16; c++) hp[c] = make_float4(0.f, 0.f, 0.f, 0.f);
        }
    }
}

// top-10 of 64 per query; builds chg list + zeroes H1 rows on first-set
__global__ void k_topk(const int* __restrict__ edges1, const float* __restrict__ score,
                       float* __restrict__ out) {
    int w = (blockIdx.x * blockDim.x + threadIdx.x) >> 5;
    int lane = threadIdx.x & 31;
    if (w >= NQ) return;
    int g0 = lane, g1 = lane + 32;
    int e0 = w*64 + g0, e1 = w*64 + g1;
    int s0 = g_esrc[e0], s1 = g_esrc[e1];
    float tr0 = g_logit[e0] / g_segsum[s0];
    float tr1 = g_logit[e1] / g_segsum[s1];
    float v0 = tr0 * score[s0];
    float v1 = tr1 * score[s1];
    int myG = 0; float myTr = 0.f;
    for (int k = 0; k < KSEL; k++) {
        float bv; int bg; float bt;
        if (v0 >= v1) { bv = v0; bg = g0; bt = tr0; }
        else          { bv = v1; bg = g1; bt = tr1; }
        for (int o = 16; o; o >>= 1) {
            float ov = __shfl_xor_sync(~0u, bv, o);
            int   og = __shfl_xor_sync(~0u, bg, o);
            float ot = __shfl_xor_sync(~0u, bt, o);
            if (ov > bv || (ov == bv && og < bg)) { bv = ov; bg = og; bt = ot; }
        }
        if (lane == k) { myG = bg; myTr = bt; }
        if (g0 == bg) v0 = -__int_as_float(0x7f800000);
        if (g1 == bg) v1 = -__int_as_float(0x7f800000);
    }
    if (lane < KSEL) {
        int orig = w*64 + myG;
        int oi = w*KSEL + lane;
        int src = g_esrc[orig], dst = g_edst[orig];
        g_psrc[oi] = src; g_pdst[oi] = dst; g_ptrans[oi] = myTr;
        if (atomicExch(&g_has[src], 1) == 0) {
            int idx = atomicAdd(&g_ncnt, 1);
            g_chg[idx] = src;
            float4* hp = (float4*)(g_H1 + (size_t)src*64);
            #pragma unroll
            for (int c = 0; c < 16; c++) hp[c] = make_float4(0.f, 0.f, 0.f, 0.f);
        }
        atomicAdd(out + dst, myTr * score[src]);
        float* pe = out + OFF_PE + (size_t)oi*8;
        for (int c = 0; c < 8; c++) pe[c] = (float)edges1[orig*8 + c];
        out[OFF_OI + oi] = (float)orig;
    }
}

// pruned-edge scatter: half-warp per edge, float4 loads + 2x red2
__global__ void k_scatter1(const float* __restrict__ H) {
    int hw = (blockIdx.x * blockDim.x + threadIdx.x) >> 4;
    int sub = threadIdx.x & 15;
    if (hw >= NQ*KSEL) return;
    int src = g_psrc[hw], dst = g_pdst[hw];
    float t = g_ptrans[hw];
    float4 hv = *(const float4*)(H + (size_t)dst*64 + sub*4);
    red2(&g_H1[(size_t)src*64 + sub*4],     t * hv.x, t * hv.y);
    red2(&g_H1[(size_t)src*64 + sub*4 + 2], t * hv.z, t * hv.w);
}

// delta nodeT: 64 gathered rows x 192 cols per block, 8x6 pairs
__global__ void k_dgemm(const float* __restrict__ Hold) {
    extern __shared__ float smD[];
    float (*sAT)[68] = (float(*)[68])smD;
    float (*sB)[196] = (float(*)[196])(smD + 64*68);
    __shared__ int snode[64];
    int cnt = g_ncnt;
    int rb = blockIdx.x * 64;
    if (rb >= cnt) return;
    int t = threadIdx.x;
    if (t < 64) snode[t] = (rb + t < cnt) ? g_chg[rb + t] : -1;
    __syncthreads();
    {
        int r = t >> 4, c4 = (t & 15) * 4;
        for (int rr = r; rr < 64; rr += 16) {
            int node = snode[rr];
            float4 av = make_float4(0.f, 0.f, 0.f, 0.f);
            if (node >= 0) {
                float4 a = *(const float4*)(g_H1 + (size_t)node*64 + c4);
                float4 b = *(const float4*)(Hold + (size_t)node*64 + c4);
                av = make_float4(a.x - b.x, a.y - b.y, a.z - b.z, a.w - b.w);
            }
            sAT[c4+0][rr] = av.x; sAT[c4+1][rr] = av.y;
            sAT[c4+2][rr] = av.z; sAT[c4+3][rr] = av.w;
        }
        for (int kk = r; kk < 64; kk += 16) {
            #pragma unroll
            for (int co = 0; co < 3; co++)
                *(float4*)&sB[kk][c4 + co*64] = *(const float4*)(g_B1 + (size_t)kk*192 + c4 + co*64);
        }
    }
    __syncthreads();
    int tx = t & 31, ty = t >> 5;
    int r0 = ty * 8, c0 = tx * 6;
    u64 accd[4][3] = {};
    u64 acca[4][3] = {};
    #pragma unroll 4
    for (int k = 0; k < 64; k++) {
        u64 a2[4];
        #pragma unroll
        for (int p = 0; p < 4; p++) a2[p] = *(const u64*)&sAT[k][r0 + 2*p];
        u64 b2[3], bs[3];
        #pragma unroll
        for (int j = 0; j < 3; j++) {
            b2[j] = *(const u64*)&sB[k][c0 + 2*j];
            bs[j] = swp(b2[j]);
        }
        #pragma unroll
        for (int p = 0; p < 4; p++)
            #pragma unroll
            for (int j = 0; j < 3; j++) {
                fma2(accd[p][j], a2[p], b2[j]);
                fma2(acca[p][j], a2[p], bs[j]);
            }
    }
    #pragma unroll
    for (int p = 0; p < 4; p++) {
        int n0 = snode[r0 + 2*p], n1 = snode[r0 + 2*p + 1];
        #pragma unroll
        for (int j = 0; j < 3; j++) {
            float2 d = upk(accd[p][j]), an = upk(acca[p][j]);
            if (n0 >= 0) {
                float* C0 = g_nodeT + (size_t)n0*192 + c0 + 2*j;
                float2 co = upk(*(u64*)C0);
                *(u64*)C0 = pk2(co.x + d.x, co.y + an.x);
            }
            if (n1 >= 0) {
                float* C1 = g_nodeT + (size_t)n1*192 + c0 + 2*j;
                float2 co = upk(*(u64*)C1);
                *(u64*)C1 = pk2(co.x + an.y, co.y + d.y);
            }
        }
    }
}

// edges0 scatter: half-warp per edge, float4 loads + 2x red2
__global__ void k_scatter0(const float* __restrict__ H) {
    int hw = (blockIdx.x * blockDim.x + threadIdx.x) >> 4;
    int sub = threadIdx.x & 15;
    if (hw >= E0N) return;
    int src = g_esrc[hw], dst = g_edst[hw];
    float t = g_logit[hw] / g_segsum0[src];
    const float* Hd = g_has[dst] ? (const float*)g_H1 : H;
    float4 hv = *(const float4*)(Hd + (size_t)dst*64 + sub*4);
    red2(&g_H2[(size_t)src*64 + sub*4],     t * hv.x, t * hv.y);
    red2(&g_H2[(size_t)src*64 + sub*4 + 2], t * hv.z, t * hv.w);
}

// final GEMM: 128 rows/block (2 tiles), 64 thr/tile, 8x8 pairs, virtual A select
__global__ void k_gemmF(const float* __restrict__ H, float* __restrict__ C,
                        const float* __restrict__ bias) {
    extern __shared__ float smF[];
    float* sA = smF;
    float (*sB)[68] = (float(*)[68])(smF + 2*64*68);
    int t = threadIdx.x;
    int rb = blockIdx.x * 128;
    {
        int r = t >> 4, c4 = (t & 15) * 4;
        for (int rr = r; rr < 128; rr += 8) {
            int node = rb + rr; if (node >= N_NODES) node = N_NODES - 1;
            const float* Ap = g_has0[node] ? (const float*)g_H2
                             : (g_has[node] ? (const float*)g_H1 : H);
            float4 av = *(const float4*)(Ap + (size_t)node*64 + c4);
            float* sAg = sA + (rr >> 6)*(64*68);
            int lrow = rr & 63;
            sAg[(c4+0)*68 + lrow] = av.x;
            sAg[(c4+1)*68 + lrow] = av.y;
            sAg[(c4+2)*68 + lrow] = av.z;
            sAg[(c4+3)*68 + lrow] = av.w;
        }
        for (int kk = r; kk < 64; kk += 8)
            *(float4*)&sB[kk][c4] = *(const float4*)(g_BL + kk*64 + c4);
    }
    __syncthreads();
    int g = t >> 6, gt = t & 63;
    int tx = gt & 7, ty = gt >> 3;
    int r0 = ty * 8, c0 = tx * 8;
    const float (*sAg)[68] = (const float(*)[68])(sA + g*(64*68));
    u64 accd[4][4] = {};
    u64 acca[4][4] = {};
    #pragma unroll 4
    for (int k = 0; k < 64; k++) {
        u64 a2[4];
        #pragma unroll
        for (int p = 0; p < 4; p++) a2[p] = *(const u64*)&sAg[k][r0 + 2*p];
        u64 b2[4], bs[4];
        #pragma unroll
        for (int j = 0; j < 4; j++) {
            b2[j] = *(const u64*)&sB[k][c0 + 2*j];
            bs[j] = swp(b2[j]);
        }
        #pragma unroll
        for (int p = 0; p < 4; p++)
            #pragma unroll
            for (int j = 0; j < 4; j++) {
                fma2(accd[p][j], a2[p], b2[j]);
                fma2(acca[p][j], a2[p], bs[j]);
            }
    }
    float bl[8];
    #pragma unroll
    for (int j = 0; j < 8; j++) bl[j] = bias[c0 + j];
    #pragma unroll
    for (int p = 0; p < 4; p++) {
        int row0 = rb + g*64 + r0 + 2*p;
        float o0[8], o1[8];
        #pragma unroll
        for (int j = 0; j < 4; j++) {
            float2 d = upk(accd[p][j]), an = upk(acca[p][j]);
            o0[2*j] = d.x;  o0[2*j+1] = an.x;
            o1[2*j] = an.y; o1[2*j+1] = d.y;
        }
        #pragma unroll
        for (int j = 0; j < 8; j++) {
            float x = o0[j] + bl[j]; o0[j] = x >= 0.f ? x : 0.01f * x;
            float y = o1[j] + bl[j]; o1[j] = y >= 0.f ? y : 0.01f * y;
        }
        if (row0 < N_NODES) {
            float* Cp = C + (size_t)row0*64 + c0;
            *(float4*)Cp     = make_float4(o0[0], o0[1], o0[2], o0[3]);
            *(float4*)(Cp+4) = make_float4(o0[4], o0[5], o0[6], o0[7]);
        }
        if (row0 + 1 < N_NODES) {
            float* Cp = C + (size_t)(row0+1)*64 + c0;
            *(float4*)Cp     = make_float4(o1[0], o1[1], o1[2], o1[3]);
            *(float4*)(Cp+4) = make_float4(o1[4], o1[5], o1[6], o1[7]);
        }
    }
}

// ---------------- launch ----------------
extern "C" void kernel_launch(void* const* d_in, const int* in_sizes, int n_in,
                              void* d_out, int out_size) {
    const float* score = (const float*)d_in[0];
    const float* H     = (const float*)d_in[1];
    const float* rel0  = (const float*)d_in[2];
    const float* rel1  = (const float*)d_in[3];
    const float* prior = (const float*)d_in[4];
    const float* qst   = (const float*)d_in[5];
    const float* qrl   = (const float*)d_in[6];
    const float* Wq    = (const float*)d_in[7];
    const float* Wk    = (const float*)d_in[8];
    const float* Wlin  = (const float*)d_in[9];
    const float* blin  = (const float*)d_in[10];
    const float* gamma = (const float*)d_in[11];
    const int*   e0    = (const int*)d_in[12];
    const int*   e1    = (const int*)d_in[13];
    float* out = (float*)d_out;

    const int USMEM = (64*68 + 64*196) * 4;   // 67584 B
    const int FSMEM = 3*64*68*4;              // 52224 B
    cudaFuncSetAttribute(k_uberB, cudaFuncAttributeMaxDynamicSharedMemorySize, USMEM);
    cudaFuncSetAttribute(k_dgemm, cudaFuncAttributeMaxDynamicSharedMemorySize, USMEM);
    cudaFuncSetAttribute(k_gemmF, cudaFuncAttributeMaxDynamicSharedMemorySize, FSMEM);

    k_prep<<<NBI + 32, 256>>>(out, Wq, Wk);
    k_buildB<<<(64*192 + 2*64*64 + 128*320 + 255)/256, 256>>>(Wlin);
    k_uberB<<<NB_N + NB_QT + NB_QD, 256, USMEM>>>(H, rel1, rel0, qst, qrl);

    // ---- stage 1 ----
    k_logits1<<<E1N/16, 256>>>(e1, rel1, H, prior, gamma);
    k_pass2<<<E1N/256, 256>>>(0, E1N);
    k_topk<<<NQ/8, 256>>>(e1, score, out);
    k_scatter1<<<(NQ*KSEL)/16, 256>>>(H);

    // ---- stage 0 ----
    k_dgemm<<<(NQ*KSEL)/64, 256, USMEM>>>(H);
    k_logits0<<<E0N/16, 256>>>(e0, rel0, H, E0N);
    k_pass2<<<E0N/256, 256>>>(1, E0N);
    k_scatter0<<<E0N/16, 256>>>(H);

    // ---- final ----
    k_gemmF<<<(N_NODES + 127)/128, 128, FSMEM>>>(H, out + OFF_REPR, blin);
}